// round 1
// baseline (speedup 1.0000x reference)
#include <cuda_runtime.h>
#include <cstdint>

// ---------------- constants ----------------
#define CINV   128
#define COUTV  64
#define HN     256
#define WN     256
#define HPAD   258
#define WPAD   258
#define NPTS   100000
#define BATCH  4
#define TOTPTS 400000
#define PLANE_PAD (HPAD*WPAD)          // 66564
#define GRID_ELEMS ((size_t)BATCH*COUTV*HPAD*WPAD)   // 17,040,384

// ---------------- device scratch (no allocations allowed) ----------------
__device__ float g_bev[GRID_ELEMS];
__device__ float g_tmp[GRID_ELEMS];
__device__ float g_w1t[64*132];   // [co][k] padded to 132
__device__ float g_w2t[64*68];    // [co][c] padded to 68
__device__ float g_wc1[9*64*64];  // [tap][ci][co], BN-folded
__device__ float g_wc2[9*64*64];
__device__ float g_fb1[64];
__device__ float g_cb1[64];
__device__ float g_cb2[64];

// ---------------- f32x2 helpers (Blackwell packed fp32) ----------------
#define FMA2(d, a, b) asm("fma.rn.f32x2 %0, %1, %2, %0;" : "+l"(d) : "l"(a), "l"(b))
#define UNPACK2(lo, hi, v) asm("mov.b64 {%0, %1}, %2;" : "=f"(lo), "=f"(hi) : "l"(v))
__device__ __forceinline__ unsigned long long PACK2(float x, float y){
    unsigned long long r;
    asm("mov.b64 %0, {%1, %2};" : "=l"(r) : "f"(x), "f"(y));
    return r;
}

// ---------------- prep: fold BN into weights, transpose layouts ----------------
__global__ void prep_kernel(
    const float* __restrict__ w1, const float* __restrict__ b1,
    const float* __restrict__ g1, const float* __restrict__ be1,
    const float* __restrict__ m1, const float* __restrict__ v1,
    const float* __restrict__ w2,
    const float* __restrict__ cw1, const float* __restrict__ cb1,
    const float* __restrict__ cg1, const float* __restrict__ cbe1,
    const float* __restrict__ cm1, const float* __restrict__ cv1,
    const float* __restrict__ cw2, const float* __restrict__ cb2,
    const float* __restrict__ cg2, const float* __restrict__ cbe2,
    const float* __restrict__ cm2, const float* __restrict__ cv2)
{
    int idx = blockIdx.x*blockDim.x + threadIdx.x;
    if (idx < 64*132){
        int co = idx/132, k = idx - co*132;
        float s = g1[co]*rsqrtf(v1[co]+1e-5f);
        g_w1t[idx] = (k < 131) ? w1[k*64+co]*s : 0.f;
        return;
    }
    idx -= 64*132;
    if (idx < 64*68){
        int co = idx/68, c = idx - co*68;
        g_w2t[idx] = (c < 64) ? w2[c*64+co] : 0.f;
        return;
    }
    idx -= 64*68;
    if (idx < 9*64*64){
        int co = idx & 63, ci = (idx>>6)&63, t = idx>>12;
        float s = cg1[co]*rsqrtf(cv1[co]+1e-5f);
        g_wc1[idx] = cw1[(co*64+ci)*9 + t]*s;
        return;
    }
    idx -= 9*64*64;
    if (idx < 9*64*64){
        int co = idx & 63, ci = (idx>>6)&63, t = idx>>12;
        float s = cg2[co]*rsqrtf(cv2[co]+1e-5f);
        g_wc2[idx] = cw2[(co*64+ci)*9 + t]*s;
        return;
    }
    idx -= 9*64*64;
    if (idx < 64){
        float s = g1[idx]*rsqrtf(v1[idx]+1e-5f);
        g_fb1[idx] = (b1[idx]-m1[idx])*s + be1[idx];
        return;
    }
    idx -= 64;
    if (idx < 64){
        float s = cg1[idx]*rsqrtf(cv1[idx]+1e-5f);
        g_cb1[idx] = (cb1[idx]-cm1[idx])*s + cbe1[idx];
        return;
    }
    idx -= 64;
    if (idx < 64){
        float s = cg2[idx]*rsqrtf(cv2[idx]+1e-5f);
        g_cb2[idx] = (cb2[idx]-cm2[idx])*s + cbe2[idx];
    }
}

// ---------------- zero both padded grid buffers ----------------
__global__ void zero_kernel(){
    size_t i = (size_t)blockIdx.x*blockDim.x + threadIdx.x;
    size_t n4 = GRID_ELEMS/4;
    float4 z = make_float4(0.f,0.f,0.f,0.f);
    if (i < n4){
        ((float4*)g_bev)[i] = z;
        ((float4*)g_tmp)[i] = z;
    }
}

// ---------------- point MLP + scatter-max ----------------
#define PTS_PER_BLOCK 1024
__global__ __launch_bounds__(256)
void mlp_scatter_kernel(const float* __restrict__ points,
                        const float* __restrict__ features,
                        const float* __restrict__ b2)
{
    extern __shared__ float sm[];
    float* s_w1t  = sm;                 // 8448
    float* s_w2t  = s_w1t + 64*132;     // 4352
    float* s_fb1  = s_w2t + 64*68;      // 64
    float* s_b2   = s_fb1 + 64;         // 64
    float* s_comb = s_b2 + 64;          // 4*132
    float* s_h    = s_comb + 4*132;     // 4*64
    int*   s_info = (int*)(s_h + 4*64); // 4

    int tid = threadIdx.x;
    for (int i = tid; i < 64*132; i += 256) s_w1t[i] = g_w1t[i];
    for (int i = tid; i < 64*68;  i += 256) s_w2t[i] = g_w2t[i];
    if (tid < 64){ s_fb1[tid] = g_fb1[tid]; s_b2[tid] = b2[tid]; }
    __syncthreads();

    int base = blockIdx.x * PTS_PER_BLOCK;
    int p = tid >> 6;
    int j = tid & 63;

    for (int it = 0; it < PTS_PER_BLOCK/4; ++it){
        int g0 = base + it*4;
        // phase A: stage features + pos + cell info
        if (tid < 128){
            int pp = tid >> 5, c4 = tid & 31;
            int g = g0 + pp;
            if (g < TOTPTS)
                ((float4*)&s_comb[pp*132])[c4] =
                    ((const float4*)(features + (size_t)g*128))[c4];
        } else if (tid < 132){
            int pp = tid - 128;
            int g = g0 + pp;
            int info = -1;
            if (g < TOTPTS){
                float x = points[g*3+0], y = points[g*3+1], z = points[g*3+2];
                bool valid = (x >= -50.f) && (x < 50.f) && (y >= -50.f) &&
                             (y < 50.f) && (z >= -3.f) && (z < 5.f);
                s_comb[pp*132+128] = __fdiv_rn(x + 50.f, 100.f);
                s_comb[pp*132+129] = __fdiv_rn(y + 50.f, 100.f);
                s_comb[pp*132+130] = __fdiv_rn(z + 3.f, 8.f);
                s_comb[pp*132+131] = 0.f;
                if (valid){
                    int col = (int)__fdiv_rn(x + 50.f, 0.390625f);
                    int row = (int)__fdiv_rn(y + 50.f, 0.390625f);
                    col = min(max(col,0),255); row = min(max(row,0),255);
                    info = (row<<9) | col;
                }
            }
            s_info[pp] = info;
        }
        __syncthreads();

        // layer 1 (f32x2 over k)
        unsigned long long acc = 0ULL;
        const float* cw = s_w1t + j*132;
        const unsigned long long* cx = (const unsigned long long*)&s_comb[p*132];
        #pragma unroll 8
        for (int k4 = 0; k4 < 32; ++k4){
            ulonglong2 wv = *(const ulonglong2*)(cw + k4*4);
            FMA2(acc, cx[2*k4],   wv.x);
            FMA2(acc, cx[2*k4+1], wv.y);
        }
        float lo, hi; UNPACK2(lo, hi, acc);
        float a = lo + hi;
        a += s_comb[p*132+128]*cw[128];
        a += s_comb[p*132+129]*cw[129];
        a += s_comb[p*132+130]*cw[130];
        a += s_fb1[j];
        s_h[p*64 + j] = fmaxf(a, 0.f);
        __syncthreads();

        // layer 2
        unsigned long long acc2 = 0ULL;
        const float* cw2 = s_w2t + j*68;
        const unsigned long long* hx = (const unsigned long long*)&s_h[p*64];
        #pragma unroll 8
        for (int c4 = 0; c4 < 16; ++c4){
            ulonglong2 wv = *(const ulonglong2*)(cw2 + c4*4);
            FMA2(acc2, hx[2*c4],   wv.x);
            FMA2(acc2, hx[2*c4+1], wv.y);
        }
        UNPACK2(lo, hi, acc2);
        float v = lo + hi + s_b2[j];
        float val = fmaxf(v, 0.f);
        int info = s_info[p];
        if (info >= 0 && val > 0.f){
            int g = g0 + p;
            int row = info >> 9, col = info & 511;
            int b = g / NPTS;
            size_t o = ((size_t)(b*64 + j)*HPAD + row + 1)*WPAD + col + 1;
            atomicMax((unsigned int*)&g_bev[o], __float_as_uint(val));
        }
        __syncthreads();   // protect s_comb/s_h/s_info before next iteration
    }
}

// ---------------- 3x3 conv (BN-folded) + ReLU ----------------
// in: NCHW padded 258x258 (zero halo). out: padded interior (conv1) or
// plain NCHW 256x256 (conv2 -> d_out). Tile 4x32, thread = 1 pixel, 64 ch.
#define TILE_H 4
#define TILE_W 32
#define CONV_SMEM_FLOATS (64*204 + 9*16*64 + 64)

template<bool PADOUT>
__global__ __launch_bounds__(128)
void conv_kernel(const float* __restrict__ in, const float* __restrict__ wfold,
                 const float* __restrict__ bias, float* __restrict__ out)
{
    extern __shared__ float sm[];
    float* s_in   = sm;                 // 64 * 204 (ci-major, 6x34 pixels)
    float* s_w    = s_in + 64*204;      // 9*16*64
    float* s_bias = s_w + 9*16*64;      // 64

    int tid = threadIdx.x;
    int tx = tid & 31, ty = tid >> 5;
    int b = blockIdx.z;
    int row0 = blockIdx.y * TILE_H;     // top halo row (padded coords)
    int col0 = blockIdx.x * TILE_W;     // left halo col

    // ---- load input tile: per-(ci,row) coalesced 34-float segments ----
    {
        const float* inb = in + (size_t)b*64*PLANE_PAD;
        for (int job = ty; job < 64*6; job += 4){
            int ci = job / 6, r = job - ci*6;
            const float* src = inb + ((size_t)ci*HPAD + row0 + r)*WPAD + col0;
            float* dst = s_in + ci*204 + r*34;
            dst[tx] = src[tx];
            if (tx < 2) dst[32+tx] = src[32+tx];
        }
        if (tid < 64) s_bias[tid] = bias[tid];
    }

    unsigned long long acc[32];
    #pragma unroll
    for (int i = 0; i < 32; ++i) acc[i] = 0ULL;
    int basepix = ty*34 + tx;

    for (int ch = 0; ch < 4; ++ch){          // ci chunks of 16
        __syncthreads();
        {   // load weight chunk [9][16][64]
            const float4* gw = (const float4*)wfold;
            float4* sw = (float4*)s_w;
            for (int i4 = tid; i4 < 9*16*64/4; i4 += 128){
                int t = i4 >> 8;             // 256 float4 per tap
                int rem = i4 & 255;
                sw[i4] = gw[t*1024 + ch*256 + rem];
            }
        }
        __syncthreads();
        const float* sin_c = s_in + ch*16*204;
        #pragma unroll 1
        for (int t = 0; t < 9; ++t){
            int off = (t/3)*34 + (t%3);
            const float* sx = sin_c + basepix + off;
            const float* wt = s_w + t*16*64;
            #pragma unroll 4
            for (int ci = 0; ci < 16; ++ci){
                float x = sx[ci*204];
                unsigned long long xx = PACK2(x, x);
                const ulonglong2* wp = (const ulonglong2*)(wt + ci*64);
                #pragma unroll
                for (int jj = 0; jj < 16; ++jj){
                    ulonglong2 wv = wp[jj];
                    FMA2(acc[2*jj],   xx, wv.x);
                    FMA2(acc[2*jj+1], xx, wv.y);
                }
            }
        }
    }

    // ---- store (per-channel, full-warp coalesced) ----
    int h = row0 + ty;          // output row (unpadded coords)
    int w = col0 + tx;
    #pragma unroll
    for (int jj = 0; jj < 32; ++jj){
        float lo, hi; UNPACK2(lo, hi, acc[jj]);
        int co = 2*jj;
        float v0 = fmaxf(lo + s_bias[co],   0.f);
        float v1 = fmaxf(hi + s_bias[co+1], 0.f);
        if (PADOUT){
            size_t o = ((size_t)(b*64+co)*HPAD + h+1)*WPAD + (w+1);
            out[o] = v0;
            out[o + (size_t)PLANE_PAD] = v1;
        } else {
            size_t o = ((size_t)(b*64+co)*HN + h)*WN + w;
            out[o] = v0;
            out[o + (size_t)HN*WN] = v1;
        }
    }
}

// ---------------- launch ----------------
extern "C" void kernel_launch(void* const* d_in, const int* in_sizes, int n_in,
                              void* d_out, int out_size)
{
    const float* points   = (const float*)d_in[0];
    const float* features = (const float*)d_in[1];
    const float* w1   = (const float*)d_in[2];
    const float* b1   = (const float*)d_in[3];
    const float* g1   = (const float*)d_in[4];
    const float* be1  = (const float*)d_in[5];
    const float* m1   = (const float*)d_in[6];
    const float* v1   = (const float*)d_in[7];
    const float* w2   = (const float*)d_in[8];
    const float* b2   = (const float*)d_in[9];
    const float* cw1  = (const float*)d_in[10];
    const float* cb1  = (const float*)d_in[11];
    const float* cg1  = (const float*)d_in[12];
    const float* cbe1 = (const float*)d_in[13];
    const float* cm1  = (const float*)d_in[14];
    const float* cv1  = (const float*)d_in[15];
    const float* cw2  = (const float*)d_in[16];
    const float* cb2  = (const float*)d_in[17];
    const float* cg2  = (const float*)d_in[18];
    const float* cbe2 = (const float*)d_in[19];
    const float* cm2  = (const float*)d_in[20];
    const float* cv2  = (const float*)d_in[21];
    float* out = (float*)d_out;

    // resolve device-global scratch addresses (no allocations)
    void *p_bev, *p_tmp, *p_wc1, *p_wc2, *p_cb1, *p_cb2;
    cudaGetSymbolAddress(&p_bev, g_bev);
    cudaGetSymbolAddress(&p_tmp, g_tmp);
    cudaGetSymbolAddress(&p_wc1, g_wc1);
    cudaGetSymbolAddress(&p_wc2, g_wc2);
    cudaGetSymbolAddress(&p_cb1, g_cb1);
    cudaGetSymbolAddress(&p_cb2, g_cb2);

    int mlp_smem  = (64*132 + 64*68 + 64 + 64 + 4*132 + 4*64 + 4) * 4;
    int conv_smem = CONV_SMEM_FLOATS * 4;
    cudaFuncSetAttribute(mlp_scatter_kernel,
        cudaFuncAttributeMaxDynamicSharedMemorySize, mlp_smem);
    cudaFuncSetAttribute(conv_kernel<true>,
        cudaFuncAttributeMaxDynamicSharedMemorySize, conv_smem);
    cudaFuncSetAttribute(conv_kernel<false>,
        cudaFuncAttributeMaxDynamicSharedMemorySize, conv_smem);

    // 1) fold weights
    int prep_total = 64*132 + 64*68 + 2*9*64*64 + 3*64;
    prep_kernel<<<(prep_total+255)/256, 256>>>(
        w1,b1,g1,be1,m1,v1, w2,
        cw1,cb1,cg1,cbe1,cm1,cv1,
        cw2,cb2,cg2,cbe2,cm2,cv2);

    // 2) zero grid + scratch
    size_t n4 = GRID_ELEMS/4;
    zero_kernel<<<(int)((n4+255)/256), 256>>>();

    // 3) point MLP + scatter-max
    int mlp_blocks = (TOTPTS + PTS_PER_BLOCK - 1) / PTS_PER_BLOCK;
    mlp_scatter_kernel<<<mlp_blocks, 256, mlp_smem>>>(points, features, b2);

    // 4) conv1: g_bev -> g_tmp (padded)
    dim3 cgrid(WN/TILE_W, HN/TILE_H, BATCH);
    conv_kernel<true><<<cgrid, 128, conv_smem>>>(
        (const float*)p_bev, (const float*)p_wc1, (const float*)p_cb1,
        (float*)p_tmp);

    // 5) conv2: g_tmp -> d_out (NCHW)
    conv_kernel<false><<<cgrid, 128, conv_smem>>>(
        (const float*)p_tmp, (const float*)p_wc2, (const float*)p_cb2,
        out);
}

// round 3
// speedup vs baseline: 1.8559x; 1.8559x over previous
#include <cuda_runtime.h>
#include <cstdint>

// ---------------- constants ----------------
#define HN     256
#define WN     256
#define HPAD   258
#define WPAD   258
#define NPTS   100000
#define BATCH  4
#define TOTPTS 400000
#define PLANE_PAD (HPAD*WPAD)                        // 66564
#define GRID_ELEMS ((size_t)BATCH*64*HPAD*WPAD)      // 17,040,384

// ---------------- device scratch ----------------
__device__ float g_bev[GRID_ELEMS];
__device__ float g_tmp[GRID_ELEMS];   // halo stays .bss-zero; interior rewritten each run
__device__ float g_w1t[64*132];       // [co][k] padded to 132, BN-folded
__device__ float g_w2t[64*68];        // [co][c] padded to 68
__device__ float g_wc1[9*64*64];      // [tap][ci][co], BN-folded
__device__ float g_wc2[9*64*64];
__device__ float g_fb1[64];
__device__ float g_cb1[64];
__device__ float g_cb2[64];

// ---------------- f32x2 helpers ----------------
#define FMA2(d, a, b) asm("fma.rn.f32x2 %0, %1, %2, %0;" : "+l"(d) : "l"(a), "l"(b))
#define UNPACK2(lo, hi, v) asm("mov.b64 {%0, %1}, %2;" : "=f"(lo), "=f"(hi) : "l"(v))
__device__ __forceinline__ unsigned long long PACK2(float x, float y){
    unsigned long long r;
    asm("mov.b64 %0, {%1, %2};" : "=l"(r) : "f"(x), "f"(y));
    return r;
}

// ---------------- prep: fold BN into weights, transpose layouts ----------------
__global__ void prep_kernel(
    const float* __restrict__ w1, const float* __restrict__ b1,
    const float* __restrict__ g1, const float* __restrict__ be1,
    const float* __restrict__ m1, const float* __restrict__ v1,
    const float* __restrict__ w2,
    const float* __restrict__ cw1, const float* __restrict__ cb1,
    const float* __restrict__ cg1, const float* __restrict__ cbe1,
    const float* __restrict__ cm1, const float* __restrict__ cv1,
    const float* __restrict__ cw2, const float* __restrict__ cb2,
    const float* __restrict__ cg2, const float* __restrict__ cbe2,
    const float* __restrict__ cm2, const float* __restrict__ cv2)
{
    int idx = blockIdx.x*blockDim.x + threadIdx.x;
    if (idx < 64*132){
        int co = idx/132, k = idx - co*132;
        float s = g1[co]*rsqrtf(v1[co]+1e-5f);
        g_w1t[idx] = (k < 131) ? w1[k*64+co]*s : 0.f;
        return;
    }
    idx -= 64*132;
    if (idx < 64*68){
        int co = idx/68, c = idx - co*68;
        g_w2t[idx] = (c < 64) ? w2[c*64+co] : 0.f;
        return;
    }
    idx -= 64*68;
    if (idx < 9*64*64){
        int co = idx & 63, ci = (idx>>6)&63, t = idx>>12;
        float s = cg1[co]*rsqrtf(cv1[co]+1e-5f);
        g_wc1[idx] = cw1[(co*64+ci)*9 + t]*s;
        return;
    }
    idx -= 9*64*64;
    if (idx < 9*64*64){
        int co = idx & 63, ci = (idx>>6)&63, t = idx>>12;
        float s = cg2[co]*rsqrtf(cv2[co]+1e-5f);
        g_wc2[idx] = cw2[(co*64+ci)*9 + t]*s;
        return;
    }
    idx -= 9*64*64;
    if (idx < 64){
        float s = g1[idx]*rsqrtf(v1[idx]+1e-5f);
        g_fb1[idx] = (b1[idx]-m1[idx])*s + be1[idx];
        return;
    }
    idx -= 64;
    if (idx < 64){
        float s = cg1[idx]*rsqrtf(cv1[idx]+1e-5f);
        g_cb1[idx] = (cb1[idx]-cm1[idx])*s + cbe1[idx];
        return;
    }
    idx -= 64;
    if (idx < 64){
        float s = cg2[idx]*rsqrtf(cv2[idx]+1e-5f);
        g_cb2[idx] = (cb2[idx]-cm2[idx])*s + cbe2[idx];
    }
}

// ---------------- zero BEV grid ----------------
__global__ void zero_kernel(){
    size_t i = (size_t)blockIdx.x*blockDim.x + threadIdx.x;
    size_t n4 = GRID_ELEMS/4;
    if (i < n4) ((float4*)g_bev)[i] = make_float4(0.f,0.f,0.f,0.f);
}

// ---------------- point MLP + scatter-max ----------------
// 256 threads: cg = tid&31 (co pair 2cg,2cg+1), pg = tid>>5 (8 pts each).
#define MLP_ITERS 4
#define NCHUNKS   6250            // 400000/64
#define MLP_SMEM_FLOATS (64*132 + 64*68 + 64*132 + 64*68 + 64 + 64 + 64)

__global__ __launch_bounds__(256, 2)
void mlp_scatter_kernel(const float* __restrict__ points,
                        const float* __restrict__ features,
                        const float* __restrict__ b2)
{
    extern __shared__ float sm[];
    float* s_w1t  = sm;                  // [64][132]
    float* s_w2t  = s_w1t + 64*132;      // [64][68]
    float* s_comb = s_w2t + 64*68;       // [64][132]
    float* s_h    = s_comb + 64*132;     // [64][68]
    float* s_fb1  = s_h + 64*68;         // 64
    float* s_b2   = s_fb1 + 64;          // 64
    int*   s_info = (int*)(s_b2 + 64);   // 64

    int tid = threadIdx.x;
    int cg = tid & 31;
    int pg = tid >> 5;

    for (int i = tid; i < 64*132; i += 256) s_w1t[i] = g_w1t[i];
    for (int i = tid; i < 64*68;  i += 256) s_w2t[i] = g_w2t[i];
    if (tid < 64){ s_fb1[tid] = g_fb1[tid]; s_b2[tid] = b2[tid]; }
    __syncthreads();

    const float* w1a = s_w1t + (2*cg)*132;
    const float* w1b = w1a + 132;
    const float* w2a = s_w2t + (2*cg)*68;
    const float* w2b = w2a + 68;

    for (int it = 0; it < MLP_ITERS; ++it){
        int chunk = blockIdx.x*MLP_ITERS + it;
        if (chunk >= NCHUNKS) break;                 // uniform per block
        int g0 = chunk * 64;

        // ---- stage 64 points ----
        {
            const float4* fsrc = (const float4*)(features + (size_t)g0*128);
            #pragma unroll
            for (int i = 0; i < 8; ++i){
                int idx = tid + i*256;
                int pt = idx >> 5, c4 = idx & 31;
                ((float4*)&s_comb[pt*132])[c4] = fsrc[pt*32 + c4];
            }
            if (tid < 64){
                int g = g0 + tid;
                float x = points[(size_t)g*3+0];
                float y = points[(size_t)g*3+1];
                float z = points[(size_t)g*3+2];
                bool valid = (x >= -50.f) && (x < 50.f) && (y >= -50.f) &&
                             (y < 50.f) && (z >= -3.f) && (z < 5.f);
                s_comb[tid*132+128] = __fdiv_rn(x + 50.f, 100.f);
                s_comb[tid*132+129] = __fdiv_rn(y + 50.f, 100.f);
                s_comb[tid*132+130] = __fdiv_rn(z + 3.f, 8.f);
                s_comb[tid*132+131] = 0.f;
                int info = -1;
                if (valid){
                    int col = (int)__fdiv_rn(x + 50.f, 0.390625f);
                    int row = (int)__fdiv_rn(y + 50.f, 0.390625f);
                    col = min(max(col,0),255); row = min(max(row,0),255);
                    int b = g / NPTS;
                    info = (b<<18) | (row<<9) | col;
                }
                s_info[tid] = info;
            }
        }
        __syncthreads();

        // ---- layer 1: 8 pts x 2 co over K=132 ----
        {
            unsigned long long acc2[8][2];
            #pragma unroll
            for (int i = 0; i < 8; ++i){ acc2[i][0]=0ULL; acc2[i][1]=0ULL; }
            const float* xbase = s_comb + (pg*8)*132;
            #pragma unroll 3
            for (int k4 = 0; k4 < 33; ++k4){
                ulonglong2 wv0 = *(const ulonglong2*)(w1a + k4*4);
                ulonglong2 wv1 = *(const ulonglong2*)(w1b + k4*4);
                #pragma unroll
                for (int i = 0; i < 8; ++i){
                    ulonglong2 xv = *(const ulonglong2*)(xbase + i*132 + k4*4);
                    FMA2(acc2[i][0], xv.x, wv0.x);
                    FMA2(acc2[i][0], xv.y, wv0.y);
                    FMA2(acc2[i][1], xv.x, wv1.x);
                    FMA2(acc2[i][1], xv.y, wv1.y);
                }
            }
            float fb0 = s_fb1[2*cg], fb1v = s_fb1[2*cg+1];
            #pragma unroll
            for (int i = 0; i < 8; ++i){
                float lo, hi;
                UNPACK2(lo, hi, acc2[i][0]);
                float h0 = fmaxf(lo + hi + fb0, 0.f);
                UNPACK2(lo, hi, acc2[i][1]);
                float h1 = fmaxf(lo + hi + fb1v, 0.f);
                *(unsigned long long*)&s_h[(pg*8+i)*68 + 2*cg] = PACK2(h0, h1);
            }
        }
        __syncthreads();

        // ---- layer 2 + scatter ----
        {
            unsigned long long acc2[8][2];
            #pragma unroll
            for (int i = 0; i < 8; ++i){ acc2[i][0]=0ULL; acc2[i][1]=0ULL; }
            const float* xbase = s_h + (pg*8)*68;
            #pragma unroll 4
            for (int k4 = 0; k4 < 16; ++k4){
                ulonglong2 wv0 = *(const ulonglong2*)(w2a + k4*4);
                ulonglong2 wv1 = *(const ulonglong2*)(w2b + k4*4);
                #pragma unroll
                for (int i = 0; i < 8; ++i){
                    ulonglong2 xv = *(const ulonglong2*)(xbase + i*68 + k4*4);
                    FMA2(acc2[i][0], xv.x, wv0.x);
                    FMA2(acc2[i][0], xv.y, wv0.y);
                    FMA2(acc2[i][1], xv.x, wv1.x);
                    FMA2(acc2[i][1], xv.y, wv1.y);
                }
            }
            float bb0 = s_b2[2*cg], bb1 = s_b2[2*cg+1];
            #pragma unroll
            for (int i = 0; i < 8; ++i){
                int info = s_info[pg*8+i];
                if (info < 0) continue;
                int b   = info >> 18;
                int row = (info >> 9) & 511;
                int colc = info & 511;
                float lo, hi;
                UNPACK2(lo, hi, acc2[i][0]);
                float v0 = lo + hi + bb0;
                UNPACK2(lo, hi, acc2[i][1]);
                float v1 = lo + hi + bb1;
                size_t obase = ((size_t)(b*64 + 2*cg)*HPAD + row + 1)*WPAD + colc + 1;
                if (v0 > 0.f)
                    atomicMax((unsigned int*)&g_bev[obase], __float_as_uint(v0));
                if (v1 > 0.f)
                    atomicMax((unsigned int*)&g_bev[obase + PLANE_PAD], __float_as_uint(v1));
            }
        }
        __syncthreads();
    }
}

// ---------------- 3x3 conv (BN-folded) + ReLU, register-blocked ----------------
// 128 threads: tx=tid&31, q=tid>>5, ty=q&1, cg=q>>1.
// Thread: 2 pixels x 32 co. Tile 4x32. ci chunked by 16.
#define CONV_SMEM_FLOATS (16*6*34 + 9*16*64 + 64)

template<bool PADOUT>
__global__ __launch_bounds__(128, 4)
void conv_kernel(const float* __restrict__ in, const float* __restrict__ wfold,
                 const float* __restrict__ bias, float* __restrict__ out)
{
    extern __shared__ float sm[];
    float* s_in   = sm;                 // [16 ci][6 rows][34]
    float* s_w    = s_in + 16*6*34;     // [9][16][64]
    float* s_bias = s_w + 9*16*64;      // 64

    int tid = threadIdx.x;
    int tx = tid & 31;
    int q  = tid >> 5;
    int ty = q & 1;
    int cg = q >> 1;
    int wid = q;
    int b = blockIdx.z;
    int row0 = blockIdx.y * 4;
    int col0 = blockIdx.x * 32;

    if (tid < 64) s_bias[tid] = bias[tid];

    unsigned long long acc0[16], acc1[16];
    #pragma unroll
    for (int i = 0; i < 16; ++i){ acc0[i]=0ULL; acc1[i]=0ULL; }

    const float* inb = in + (size_t)b*64*PLANE_PAD;

    #pragma unroll 1
    for (int ch = 0; ch < 4; ++ch){
        __syncthreads();
        // input chunk: 16 ci x 6 rows x 34 cols
        #pragma unroll 1
        for (int s = wid; s < 96; s += 4){
            int ci = s / 6, r = s - ci*6;
            const float* src = inb + ((size_t)(ch*16+ci)*HPAD + row0 + r)*WPAD + col0;
            float* dst = s_in + ci*204 + r*34;
            dst[tx] = src[tx];
            if (tx < 2) dst[32+tx] = src[32+tx];
        }
        // weight chunk [9][16][64]
        {
            const float4* gw = (const float4*)wfold;
            float4* sw = (float4*)s_w;
            #pragma unroll 1
            for (int i4 = tid; i4 < 2304; i4 += 128){
                int t = i4 >> 8;
                int rem = i4 & 255;
                sw[i4] = gw[t*1024 + ch*256 + rem];
            }
        }
        __syncthreads();

        #pragma unroll 1
        for (int ci = 0; ci < 16; ++ci){
            const float* xb = s_in + ci*204 + (2*ty)*34 + tx;
            float xr[4][3];
            #pragma unroll
            for (int rr = 0; rr < 4; ++rr)
                #pragma unroll
                for (int cc = 0; cc < 3; ++cc)
                    xr[rr][cc] = xb[rr*34 + cc];

            #pragma unroll
            for (int t = 0; t < 9; ++t){
                const int dh = t/3, dw = t - dh*3;
                unsigned long long xx0 = PACK2(xr[dh][dw],   xr[dh][dw]);
                unsigned long long xx1 = PACK2(xr[dh+1][dw], xr[dh+1][dw]);
                const ulonglong2* wp =
                    (const ulonglong2*)(s_w + t*1024 + ci*64 + cg*32);
                #pragma unroll
                for (int jj = 0; jj < 8; ++jj){
                    ulonglong2 wv = wp[jj];
                    FMA2(acc0[2*jj],   xx0, wv.x);
                    FMA2(acc0[2*jj+1], xx0, wv.y);
                    FMA2(acc1[2*jj],   xx1, wv.x);
                    FMA2(acc1[2*jj+1], xx1, wv.y);
                }
            }
        }
    }

    // ---- store: 2 px x 32 co ----
    int h0 = row0 + 2*ty;
    int w  = col0 + tx;
    #pragma unroll
    for (int m = 0; m < 16; ++m){
        int co = cg*32 + 2*m;
        float bia = s_bias[co], bib = s_bias[co+1];
        float lo, hi;
        UNPACK2(lo, hi, acc0[m]);
        float a0 = fmaxf(lo + bia, 0.f);
        float a1 = fmaxf(hi + bib, 0.f);
        UNPACK2(lo, hi, acc1[m]);
        float b0 = fmaxf(lo + bia, 0.f);
        float b1 = fmaxf(hi + bib, 0.f);
        if (PADOUT){
            size_t o0 = ((size_t)(b*64+co)*HPAD + h0+1)*WPAD + (w+1);
            out[o0] = a0;
            out[o0 + (size_t)PLANE_PAD] = a1;
            out[o0 + WPAD] = b0;
            out[o0 + (size_t)PLANE_PAD + WPAD] = b1;
        } else {
            size_t o0 = ((size_t)(b*64+co)*HN + h0)*WN + w;
            out[o0] = a0;
            out[o0 + (size_t)HN*WN] = a1;
            out[o0 + WN] = b0;
            out[o0 + (size_t)HN*WN + WN] = b1;
        }
    }
}

// ---------------- launch ----------------
extern "C" void kernel_launch(void* const* d_in, const int* in_sizes, int n_in,
                              void* d_out, int out_size)
{
    const float* points   = (const float*)d_in[0];
    const float* features = (const float*)d_in[1];
    const float* w1   = (const float*)d_in[2];
    const float* b1   = (const float*)d_in[3];
    const float* g1   = (const float*)d_in[4];
    const float* be1  = (const float*)d_in[5];
    const float* m1   = (const float*)d_in[6];
    const float* v1   = (const float*)d_in[7];
    const float* w2   = (const float*)d_in[8];
    const float* b2   = (const float*)d_in[9];
    const float* cw1  = (const float*)d_in[10];
    const float* cb1  = (const float*)d_in[11];
    const float* cg1  = (const float*)d_in[12];
    const float* cbe1 = (const float*)d_in[13];
    const float* cm1  = (const float*)d_in[14];
    const float* cv1  = (const float*)d_in[15];
    const float* cw2  = (const float*)d_in[16];
    const float* cb2  = (const float*)d_in[17];
    const float* cg2  = (const float*)d_in[18];
    const float* cbe2 = (const float*)d_in[19];
    const float* cm2  = (const float*)d_in[20];
    const float* cv2  = (const float*)d_in[21];
    float* out = (float*)d_out;

    void *p_bev, *p_tmp, *p_wc1, *p_wc2, *p_cb1, *p_cb2;
    cudaGetSymbolAddress(&p_bev, g_bev);
    cudaGetSymbolAddress(&p_tmp, g_tmp);
    cudaGetSymbolAddress(&p_wc1, g_wc1);
    cudaGetSymbolAddress(&p_wc2, g_wc2);
    cudaGetSymbolAddress(&p_cb1, g_cb1);
    cudaGetSymbolAddress(&p_cb2, g_cb2);

    int mlp_smem  = MLP_SMEM_FLOATS * 4;
    int conv_smem = CONV_SMEM_FLOATS * 4;
    cudaFuncSetAttribute(mlp_scatter_kernel,
        cudaFuncAttributeMaxDynamicSharedMemorySize, mlp_smem);
    cudaFuncSetAttribute(conv_kernel<true>,
        cudaFuncAttributeMaxDynamicSharedMemorySize, conv_smem);
    cudaFuncSetAttribute(conv_kernel<false>,
        cudaFuncAttributeMaxDynamicSharedMemorySize, conv_smem);

    // 1) fold weights
    int prep_total = 64*132 + 64*68 + 2*9*64*64 + 3*64;
    prep_kernel<<<(prep_total+255)/256, 256>>>(
        w1,b1,g1,be1,m1,v1, w2,
        cw1,cb1,cg1,cbe1,cm1,cv1,
        cw2,cb2,cg2,cbe2,cm2,cv2);

    // 2) zero BEV grid
    size_t n4 = GRID_ELEMS/4;
    zero_kernel<<<(int)((n4+255)/256), 256>>>();

    // 3) point MLP + scatter-max
    int mlp_blocks = (NCHUNKS + MLP_ITERS - 1) / MLP_ITERS;
    mlp_scatter_kernel<<<mlp_blocks, 256, mlp_smem>>>(points, features, b2);

    // 4) conv1: g_bev -> g_tmp (padded)
    dim3 cgrid(WN/32, HN/4, BATCH);
    conv_kernel<true><<<cgrid, 128, conv_smem>>>(
        (const float*)p_bev, (const float*)p_wc1, (const float*)p_cb1,
        (float*)p_tmp);

    // 5) conv2: g_tmp -> d_out (NCHW)
    conv_kernel<false><<<cgrid, 128, conv_smem>>>(
        (const float*)p_tmp, (const float*)p_wc2, (const float*)p_cb2,
        out);
}

// round 4
// speedup vs baseline: 1.9979x; 1.0765x over previous
#include <cuda_runtime.h>
#include <cstdint>

// ---------------- constants ----------------
#define HN     256
#define WN     256
#define HPAD   258
#define WPAD   258
#define NPTS   100000
#define BATCH  4
#define TOTPTS 400000
#define PLANE_PAD (HPAD*WPAD)                        // 66564
#define GRID_ELEMS ((size_t)BATCH*64*HPAD*WPAD)      // 17,040,384

// ---------------- device scratch ----------------
__device__ float g_bev[GRID_ELEMS];
__device__ float g_tmp[GRID_ELEMS];   // halo stays .bss-zero; interior rewritten each run
__device__ float g_w1t[64*134];       // [co][134], k<131 valid, BN-folded, stride 134 (conflict-free)
__device__ float g_w2t[64*70];        // [co][70],  c<64 valid, stride 70
__device__ float g_wc1[9*64*64];      // [tap][ci][co], BN-folded
__device__ float g_wc2[9*64*64];
__device__ float g_fb1[64];
__device__ float g_cb1[64];
__device__ float g_cb2[64];

// ---------------- f32x2 helpers ----------------
#define FMA2(d, a, b) asm("fma.rn.f32x2 %0, %1, %2, %0;" : "+l"(d) : "l"(a), "l"(b))
#define UNPACK2(lo, hi, v) asm("mov.b64 {%0, %1}, %2;" : "=f"(lo), "=f"(hi) : "l"(v))
__device__ __forceinline__ unsigned long long PACK2(float x, float y){
    unsigned long long r;
    asm("mov.b64 %0, {%1, %2};" : "=l"(r) : "f"(x), "f"(y));
    return r;
}

// ---------------- prep: fold BN into weights, transpose layouts ----------------
__global__ void prep_kernel(
    const float* __restrict__ w1, const float* __restrict__ b1,
    const float* __restrict__ g1, const float* __restrict__ be1,
    const float* __restrict__ m1, const float* __restrict__ v1,
    const float* __restrict__ w2,
    const float* __restrict__ cw1, const float* __restrict__ cb1,
    const float* __restrict__ cg1, const float* __restrict__ cbe1,
    const float* __restrict__ cm1, const float* __restrict__ cv1,
    const float* __restrict__ cw2, const float* __restrict__ cb2,
    const float* __restrict__ cg2, const float* __restrict__ cbe2,
    const float* __restrict__ cm2, const float* __restrict__ cv2)
{
    int idx = blockIdx.x*blockDim.x + threadIdx.x;
    if (idx < 64*134){
        int co = idx/134, k = idx - co*134;
        float s = g1[co]*rsqrtf(v1[co]+1e-5f);
        g_w1t[idx] = (k < 131) ? w1[k*64+co]*s : 0.f;
        return;
    }
    idx -= 64*134;
    if (idx < 64*70){
        int co = idx/70, c = idx - co*70;
        g_w2t[idx] = (c < 64) ? w2[c*64+co] : 0.f;
        return;
    }
    idx -= 64*70;
    if (idx < 9*64*64){
        int co = idx & 63, ci = (idx>>6)&63, t = idx>>12;
        float s = cg1[co]*rsqrtf(cv1[co]+1e-5f);
        g_wc1[idx] = cw1[(co*64+ci)*9 + t]*s;
        return;
    }
    idx -= 9*64*64;
    if (idx < 9*64*64){
        int co = idx & 63, ci = (idx>>6)&63, t = idx>>12;
        float s = cg2[co]*rsqrtf(cv2[co]+1e-5f);
        g_wc2[idx] = cw2[(co*64+ci)*9 + t]*s;
        return;
    }
    idx -= 9*64*64;
    if (idx < 64){
        float s = g1[idx]*rsqrtf(v1[idx]+1e-5f);
        g_fb1[idx] = (b1[idx]-m1[idx])*s + be1[idx];
        return;
    }
    idx -= 64;
    if (idx < 64){
        float s = cg1[idx]*rsqrtf(cv1[idx]+1e-5f);
        g_cb1[idx] = (cb1[idx]-cm1[idx])*s + cbe1[idx];
        return;
    }
    idx -= 64;
    if (idx < 64){
        float s = cg2[idx]*rsqrtf(cv2[idx]+1e-5f);
        g_cb2[idx] = (cb2[idx]-cm2[idx])*s + cbe2[idx];
    }
}

// ---------------- zero BEV grid ----------------
__global__ void zero_kernel(){
    size_t i = (size_t)blockIdx.x*blockDim.x + threadIdx.x;
    size_t n4 = GRID_ELEMS/4;
    if (i < n4) ((float4*)g_bev)[i] = make_float4(0.f,0.f,0.f,0.f);
}

// ---------------- point MLP + scatter-max ----------------
// 256 threads: cg = tid&31 -> co {cg, cg+32}; pg = tid>>5 -> 8 pts each.
#define MLP_ITERS 4
#define NCHUNKS   6250            // 400000/64
#define MLP_SMEM_FLOATS (64*134 + 64*70 + 64*132 + 64*68 + 64 + 64 + 64)

__global__ __launch_bounds__(256, 2)
void mlp_scatter_kernel(const float* __restrict__ points,
                        const float* __restrict__ features,
                        const float* __restrict__ b2)
{
    extern __shared__ float sm[];
    float* s_w1t  = sm;                  // [64][134]
    float* s_w2t  = s_w1t + 64*134;      // [64][70]
    float* s_comb = s_w2t + 64*70;       // [64][132]
    float* s_h    = s_comb + 64*132;     // [64][68]
    float* s_fb1  = s_h + 64*68;         // 64
    float* s_b2   = s_fb1 + 64;          // 64
    int*   s_info = (int*)(s_b2 + 64);   // 64

    int tid = threadIdx.x;
    int cg = tid & 31;
    int pg = tid >> 5;

    for (int i = tid; i < 64*134; i += 256) s_w1t[i] = g_w1t[i];
    for (int i = tid; i < 64*70;  i += 256) s_w2t[i] = g_w2t[i];
    if (tid < 64){ s_fb1[tid] = g_fb1[tid]; s_b2[tid] = b2[tid]; }
    __syncthreads();

    const float* w1a = s_w1t + cg*134;          // co = cg
    const float* w1b = s_w1t + (cg+32)*134;     // co = cg+32
    const float* w2a = s_w2t + cg*70;
    const float* w2b = s_w2t + (cg+32)*70;

    for (int it = 0; it < MLP_ITERS; ++it){
        int chunk = blockIdx.x*MLP_ITERS + it;
        if (chunk >= NCHUNKS) break;                 // uniform per block
        int g0 = chunk * 64;

        // ---- stage 64 points ----
        {
            const float4* fsrc = (const float4*)(features + (size_t)g0*128);
            #pragma unroll
            for (int i = 0; i < 8; ++i){
                int idx = tid + i*256;
                int pt = idx >> 5, c4 = idx & 31;
                ((float4*)&s_comb[pt*132])[c4] = fsrc[pt*32 + c4];
            }
            if (tid < 64){
                int g = g0 + tid;
                float x = points[(size_t)g*3+0];
                float y = points[(size_t)g*3+1];
                float z = points[(size_t)g*3+2];
                bool valid = (x >= -50.f) && (x < 50.f) && (y >= -50.f) &&
                             (y < 50.f) && (z >= -3.f) && (z < 5.f);
                s_comb[tid*132+128] = __fdiv_rn(x + 50.f, 100.f);
                s_comb[tid*132+129] = __fdiv_rn(y + 50.f, 100.f);
                s_comb[tid*132+130] = __fdiv_rn(z + 3.f, 8.f);
                s_comb[tid*132+131] = 0.f;
                int info = -1;
                if (valid){
                    int col = (int)__fdiv_rn(x + 50.f, 0.390625f);
                    int row = (int)__fdiv_rn(y + 50.f, 0.390625f);
                    col = min(max(col,0),255); row = min(max(row,0),255);
                    int b = g / NPTS;
                    info = (b<<18) | (row<<9) | col;
                }
                s_info[tid] = info;
            }
        }
        __syncthreads();

        // ---- layer 1: 8 pts x 2 co over K=132 (conflict-free LDS.64 weights) ----
        {
            unsigned long long acc2[8][2];
            #pragma unroll
            for (int i = 0; i < 8; ++i){ acc2[i][0]=0ULL; acc2[i][1]=0ULL; }
            const float* xbase = s_comb + (pg*8)*132;
            #pragma unroll 3
            for (int k4 = 0; k4 < 33; ++k4){
                unsigned long long wv0a = *(const unsigned long long*)(w1a + k4*4);
                unsigned long long wv0b = *(const unsigned long long*)(w1a + k4*4 + 2);
                unsigned long long wv1a = *(const unsigned long long*)(w1b + k4*4);
                unsigned long long wv1b = *(const unsigned long long*)(w1b + k4*4 + 2);
                #pragma unroll
                for (int i = 0; i < 8; ++i){
                    ulonglong2 xv = *(const ulonglong2*)(xbase + i*132 + k4*4);
                    FMA2(acc2[i][0], xv.x, wv0a);
                    FMA2(acc2[i][0], xv.y, wv0b);
                    FMA2(acc2[i][1], xv.x, wv1a);
                    FMA2(acc2[i][1], xv.y, wv1b);
                }
            }
            float fb0 = s_fb1[cg], fb1v = s_fb1[cg+32];
            #pragma unroll
            for (int i = 0; i < 8; ++i){
                float lo, hi;
                UNPACK2(lo, hi, acc2[i][0]);
                float h0 = fmaxf(lo + hi + fb0, 0.f);
                UNPACK2(lo, hi, acc2[i][1]);
                float h1 = fmaxf(lo + hi + fb1v, 0.f);
                s_h[(pg*8+i)*68 + cg]      = h0;
                s_h[(pg*8+i)*68 + cg + 32] = h1;
            }
        }
        __syncthreads();

        // ---- layer 2 + scatter ----
        {
            unsigned long long acc2[8][2];
            #pragma unroll
            for (int i = 0; i < 8; ++i){ acc2[i][0]=0ULL; acc2[i][1]=0ULL; }
            const float* xbase = s_h + (pg*8)*68;
            #pragma unroll 4
            for (int k4 = 0; k4 < 16; ++k4){
                unsigned long long wv0a = *(const unsigned long long*)(w2a + k4*4);
                unsigned long long wv0b = *(const unsigned long long*)(w2a + k4*4 + 2);
                unsigned long long wv1a = *(const unsigned long long*)(w2b + k4*4);
                unsigned long long wv1b = *(const unsigned long long*)(w2b + k4*4 + 2);
                #pragma unroll
                for (int i = 0; i < 8; ++i){
                    ulonglong2 xv = *(const ulonglong2*)(xbase + i*68 + k4*4);
                    FMA2(acc2[i][0], xv.x, wv0a);
                    FMA2(acc2[i][0], xv.y, wv0b);
                    FMA2(acc2[i][1], xv.x, wv1a);
                    FMA2(acc2[i][1], xv.y, wv1b);
                }
            }
            float bb0 = s_b2[cg], bb1 = s_b2[cg+32];
            #pragma unroll
            for (int i = 0; i < 8; ++i){
                int info = s_info[pg*8+i];
                if (info < 0) continue;
                int b   = info >> 18;
                int row = (info >> 9) & 511;
                int colc = info & 511;
                float lo, hi;
                UNPACK2(lo, hi, acc2[i][0]);
                float v0 = lo + hi + bb0;
                UNPACK2(lo, hi, acc2[i][1]);
                float v1 = lo + hi + bb1;
                size_t obase = ((size_t)(b*64 + cg)*HPAD + row + 1)*WPAD + colc + 1;
                if (v0 > 0.f)
                    atomicMax((unsigned int*)&g_bev[obase], __float_as_uint(v0));
                if (v1 > 0.f)
                    atomicMax((unsigned int*)&g_bev[obase + (size_t)32*PLANE_PAD],
                              __float_as_uint(v1));
            }
        }
        __syncthreads();
    }
}

// ---------------- 3x3 conv (BN-folded) + ReLU, register-blocked ----------------
// 256 threads: tx=tid&31, q=tid>>5 (8 warps), ty=q&1, cgq=q>>1 (0..3).
// Thread: 2 pixels (rows 2ty,2ty+1) x 16 co (cgq*16..+15). Tile 4x32. ci chunks of 16.
#define CONV_SMEM_FLOATS (16*6*34 + 9*16*64 + 64)   // 3264+9216+64=12544

template<bool PADOUT>
__global__ __launch_bounds__(256, 3)
void conv_kernel(const float* __restrict__ in, const float* __restrict__ wfold,
                 const float* __restrict__ bias, float* __restrict__ out)
{
    extern __shared__ float sm[];
    float* s_in   = sm;                 // [16 ci][6 rows][34]
    float* s_w    = s_in + 16*6*34;     // [9][16][64]
    float* s_bias = s_w + 9*16*64;      // 64

    int tid = threadIdx.x;
    int tx = tid & 31;
    int q  = tid >> 5;
    int ty = q & 1;
    int cgq = q >> 1;                   // 0..3
    int b = blockIdx.z;
    int row0 = blockIdx.y * 4;
    int col0 = blockIdx.x * 32;

    if (tid < 64) s_bias[tid] = bias[tid];

    unsigned long long acc0[8], acc1[8];
    #pragma unroll
    for (int i = 0; i < 8; ++i){ acc0[i]=0ULL; acc1[i]=0ULL; }

    const float* inb = in + (size_t)b*64*PLANE_PAD;

    #pragma unroll 1
    for (int ch = 0; ch < 4; ++ch){
        __syncthreads();
        // input chunk: 16 ci x 6 rows x 34 cols (one warp per (ci,row) segment)
        #pragma unroll 1
        for (int s = q; s < 96; s += 8){
            int ci = s / 6, r = s - ci*6;
            const float* src = inb + ((size_t)(ch*16+ci)*HPAD + row0 + r)*WPAD + col0;
            float* dst = s_in + ci*204 + r*34;
            dst[tx] = src[tx];
            if (tx < 2) dst[32+tx] = src[32+tx];
        }
        // weight chunk [9][16][64]
        {
            const float4* gw = (const float4*)wfold;
            float4* sw = (float4*)s_w;
            #pragma unroll 1
            for (int i4 = tid; i4 < 2304; i4 += 256){
                int t = i4 >> 8;
                int rem = i4 & 255;
                sw[i4] = gw[t*1024 + ch*256 + rem];
            }
        }
        __syncthreads();

        #pragma unroll 1
        for (int ci = 0; ci < 16; ++ci){
            const float* xb = s_in + ci*204 + (2*ty)*34 + tx;
            float xr[4][3];
            #pragma unroll
            for (int rr = 0; rr < 4; ++rr)
                #pragma unroll
                for (int cc = 0; cc < 3; ++cc)
                    xr[rr][cc] = xb[rr*34 + cc];

            #pragma unroll
            for (int t = 0; t < 9; ++t){
                const int dh = t/3, dw = t - dh*3;
                unsigned long long xx0 = PACK2(xr[dh][dw],   xr[dh][dw]);
                unsigned long long xx1 = PACK2(xr[dh+1][dw], xr[dh+1][dw]);
                const ulonglong2* wp =
                    (const ulonglong2*)(s_w + t*1024 + ci*64 + cgq*16);
                #pragma unroll
                for (int jj = 0; jj < 4; ++jj){
                    ulonglong2 wv = wp[jj];
                    FMA2(acc0[2*jj],   xx0, wv.x);
                    FMA2(acc0[2*jj+1], xx0, wv.y);
                    FMA2(acc1[2*jj],   xx1, wv.x);
                    FMA2(acc1[2*jj+1], xx1, wv.y);
                }
            }
        }
    }

    // ---- store: 2 px x 16 co ----
    int h0 = row0 + 2*ty;
    int w  = col0 + tx;
    #pragma unroll
    for (int m = 0; m < 8; ++m){
        int co = cgq*16 + 2*m;
        float bia = s_bias[co], bib = s_bias[co+1];
        float lo, hi;
        UNPACK2(lo, hi, acc0[m]);
        float a0 = fmaxf(lo + bia, 0.f);
        float a1 = fmaxf(hi + bib, 0.f);
        UNPACK2(lo, hi, acc1[m]);
        float b0 = fmaxf(lo + bia, 0.f);
        float b1 = fmaxf(hi + bib, 0.f);
        if (PADOUT){
            size_t o0 = ((size_t)(b*64+co)*HPAD + h0+1)*WPAD + (w+1);
            out[o0] = a0;
            out[o0 + (size_t)PLANE_PAD] = a1;
            out[o0 + WPAD] = b0;
            out[o0 + (size_t)PLANE_PAD + WPAD] = b1;
        } else {
            size_t o0 = ((size_t)(b*64+co)*HN + h0)*WN + w;
            out[o0] = a0;
            out[o0 + (size_t)HN*WN] = a1;
            out[o0 + WN] = b0;
            out[o0 + (size_t)HN*WN + WN] = b1;
        }
    }
}

// ---------------- launch ----------------
extern "C" void kernel_launch(void* const* d_in, const int* in_sizes, int n_in,
                              void* d_out, int out_size)
{
    const float* points   = (const float*)d_in[0];
    const float* features = (const float*)d_in[1];
    const float* w1   = (const float*)d_in[2];
    const float* b1   = (const float*)d_in[3];
    const float* g1   = (const float*)d_in[4];
    const float* be1  = (const float*)d_in[5];
    const float* m1   = (const float*)d_in[6];
    const float* v1   = (const float*)d_in[7];
    const float* w2   = (const float*)d_in[8];
    const float* b2   = (const float*)d_in[9];
    const float* cw1  = (const float*)d_in[10];
    const float* cb1  = (const float*)d_in[11];
    const float* cg1  = (const float*)d_in[12];
    const float* cbe1 = (const float*)d_in[13];
    const float* cm1  = (const float*)d_in[14];
    const float* cv1  = (const float*)d_in[15];
    const float* cw2  = (const float*)d_in[16];
    const float* cb2  = (const float*)d_in[17];
    const float* cg2  = (const float*)d_in[18];
    const float* cbe2 = (const float*)d_in[19];
    const float* cm2  = (const float*)d_in[20];
    const float* cv2  = (const float*)d_in[21];
    float* out = (float*)d_out;

    void *p_bev, *p_tmp, *p_wc1, *p_wc2, *p_cb1, *p_cb2;
    cudaGetSymbolAddress(&p_bev, g_bev);
    cudaGetSymbolAddress(&p_tmp, g_tmp);
    cudaGetSymbolAddress(&p_wc1, g_wc1);
    cudaGetSymbolAddress(&p_wc2, g_wc2);
    cudaGetSymbolAddress(&p_cb1, g_cb1);
    cudaGetSymbolAddress(&p_cb2, g_cb2);

    int mlp_smem  = MLP_SMEM_FLOATS * 4;
    int conv_smem = CONV_SMEM_FLOATS * 4;
    cudaFuncSetAttribute(mlp_scatter_kernel,
        cudaFuncAttributeMaxDynamicSharedMemorySize, mlp_smem);
    cudaFuncSetAttribute(conv_kernel<true>,
        cudaFuncAttributeMaxDynamicSharedMemorySize, conv_smem);
    cudaFuncSetAttribute(conv_kernel<false>,
        cudaFuncAttributeMaxDynamicSharedMemorySize, conv_smem);

    // 1) fold weights
    int prep_total = 64*134 + 64*70 + 2*9*64*64 + 3*64;
    prep_kernel<<<(prep_total+255)/256, 256>>>(
        w1,b1,g1,be1,m1,v1, w2,
        cw1,cb1,cg1,cbe1,cm1,cv1,
        cw2,cb2,cg2,cbe2,cm2,cv2);

    // 2) zero BEV grid
    size_t n4 = GRID_ELEMS/4;
    zero_kernel<<<(int)((n4+255)/256), 256>>>();

    // 3) point MLP + scatter-max
    int mlp_blocks = (NCHUNKS + MLP_ITERS - 1) / MLP_ITERS;
    mlp_scatter_kernel<<<mlp_blocks, 256, mlp_smem>>>(points, features, b2);

    // 4) conv1: g_bev -> g_tmp (padded)
    dim3 cgrid(WN/32, HN/4, BATCH);
    conv_kernel<true><<<cgrid, 256, conv_smem>>>(
        (const float*)p_bev, (const float*)p_wc1, (const float*)p_cb1,
        (float*)p_tmp);

    // 5) conv2: g_tmp -> d_out (NCHW)
    conv_kernel<false><<<cgrid, 256, conv_smem>>>(
        (const float*)p_tmp, (const float*)p_wc2, (const float*)p_cb2,
        out);
}